// round 11
// baseline (speedup 1.0000x reference)
#include <cuda_runtime.h>
#include <cstdint>

#define B_ 16
#define S_ 8192
#define H_ 512
#define P_ 32
#define NSPLIT 8
#define TS 512          // s-rows per tile
#define KC 8            // h per k-chunk
#define NCH (H_/KC)     // 64 chunks
#define PSTR 516        // probe smem row stride (floats) -> conflict-free
#define XSTR 12         // x-stage row stride (floats)    -> conflict-free
#define SSTR 513        // score-stage row stride

// 16 MB scratch for scores[b*P+p][s]
__device__ float g_scores[(size_t)B_ * P_ * S_];

// ---------------- helpers ----------------
__device__ __forceinline__ void ffma2(unsigned long long& d, unsigned long long a,
                                      unsigned long long b) {
    asm("fma.rn.f32x2 %0, %1, %2, %0;" : "+l"(d) : "l"(a), "l"(b));
}
__device__ __forceinline__ float2 unpk(unsigned long long v) {
    float2 r;
    asm("mov.b64 {%0,%1}, %2;" : "=f"(r.x), "=f"(r.y) : "l"(v));
    return r;
}
__device__ __forceinline__ void cp16(float* s, const float* g) {
    unsigned sa = (unsigned)__cvta_generic_to_shared(s);
    asm volatile("cp.async.cg.shared.global [%0], [%1], 16;" :: "r"(sa), "l"(g));
}
__device__ __forceinline__ void cp_commit() { asm volatile("cp.async.commit_group;"); }
template <int N>
__device__ __forceinline__ void cp_wait() { asm volatile("cp.async.wait_group %0;" :: "n"(N)); }

// ---------------- kernel 1: scores = probes @ x^T (fp32, packed f32x2) ----------------
// grid = B_*NSPLIT (=128), block = 256. Each CTA: 1024 s-rows in 2 tiles of 512.
// Thread tile 8s x 8p: s = rowt + 64*i, p = col + 4*j (col = t&3, rowt = t>>2).
__global__ void __launch_bounds__(256, 1)
k_scores(const float* __restrict__ x, const float* __restrict__ probes) {
    extern __shared__ float sm[];
    float* psm = sm;                     // P_*PSTR   = 16512 f
    float* stg = sm + P_ * PSTR;         // 2*TS*XSTR = 12288 f
    float* scs = stg + 2 * TS * XSTR;    // P_*SSTR   = 16416 f

    const int t = threadIdx.x;
    const int col = t & 3;
    const int rowt = t >> 2;
    const int b = blockIdx.x >> 3;
    const int split = blockIdx.x & 7;
    const float* xb = x + (size_t)b * S_ * H_;

    // probes -> smem (padded rows)
    for (int idx = t; idx < P_ * H_; idx += 256) {
        psm[(idx >> 9) * PSTR + (idx & 511)] = probes[idx];
    }

    for (int tile = 0; tile < 2; ++tile) {
        const int s0 = split * 1024 + tile * TS;

        unsigned long long acc[8][8];
#pragma unroll
        for (int i = 0; i < 8; ++i)
#pragma unroll
            for (int j = 0; j < 8; ++j) acc[i][j] = 0ull;

        // prologue: chunk 0 -> buf 0
        {
#pragma unroll
            for (int q = 0; q < 4; ++q) {
                int idx = t + 256 * q;
                int row = idx >> 1, seg = (idx & 1) * 4;
                cp16(stg + row * XSTR + seg, xb + (size_t)(s0 + row) * H_ + seg);
            }
            cp_commit();
        }

#pragma unroll 1
        for (int c = 0; c < NCH; ++c) {
            if (c + 1 < NCH) {
                float* dst = stg + ((c + 1) & 1) * TS * XSTR;
                const int hc1 = (c + 1) * KC;
#pragma unroll
                for (int q = 0; q < 4; ++q) {
                    int idx = t + 256 * q;
                    int row = idx >> 1, seg = (idx & 1) * 4;
                    cp16(dst + row * XSTR + seg, xb + (size_t)(s0 + row) * H_ + hc1 + seg);
                }
                cp_commit();
                cp_wait<1>();
            } else {
                cp_wait<0>();
            }
            __syncthreads();

            const float* st = stg + (c & 1) * TS * XSTR;
            const int hc = c * KC;
#pragma unroll
            for (int u = 0; u < 2; ++u) {
                ulonglong2 pvv[8];
#pragma unroll
                for (int j = 0; j < 8; ++j)
                    pvv[j] = *(const ulonglong2*)&psm[(col + 4 * j) * PSTR + hc + u * 4];
#pragma unroll
                for (int i = 0; i < 8; ++i) {
                    ulonglong2 xv = *(const ulonglong2*)&st[(rowt + 64 * i) * XSTR + u * 4];
#pragma unroll
                    for (int j = 0; j < 8; ++j) {
                        ffma2(acc[i][j], xv.x, pvv[j].x);
                        ffma2(acc[i][j], xv.y, pvv[j].y);
                    }
                }
            }
            __syncthreads();
        }

        // finalize (even+odd partials) and stage for coalesced store
#pragma unroll
        for (int j = 0; j < 8; ++j)
#pragma unroll
            for (int i = 0; i < 8; ++i) {
                float2 v = unpk(acc[i][j]);
                scs[(col + 4 * j) * SSTR + rowt + 64 * i] = v.x + v.y;
            }
        __syncthreads();

        float* grow = g_scores + (size_t)(b * P_) * S_ + s0;
        for (int idx = t; idx < P_ * TS; idx += 256) {
            int p = idx >> 9;
            int sl = idx & 511;
            grow[(size_t)p * S_ + sl] = scs[p * SSTR + sl];
        }
        __syncthreads();
    }
}

// ---------------- kernel 2: exact softmax stats + sparse context gather ----------------
// grid = B_*P_ (=512), block = 256. One CTA per (b,p).
// Exact max and exact denominator over all 8192 scores; numerator gathers only
// entries with score >= max-20 (skipped mass < 2e-5, far below 1e-3 tolerance).
__global__ void __launch_bounds__(256, 2)
k_softmax_ctx(const float* __restrict__ x, float* __restrict__ out) {
    extern __shared__ float sm2[];
    float* ssc = sm2;                    // 8192 scores
    float* lw  = sm2 + 8192;             // weights of kept entries
    int*   lst = (int*)(sm2 + 16384);    // s-indices of kept entries (cap 8192: safe)

    __shared__ float red[8];
    __shared__ float Msh, Lsh;
    __shared__ int cnt;

    const int t = threadIdx.x;
    const int bp = blockIdx.x;
    const int b = bp >> 5;
    const int p = bp & 31;
    const float* srow = g_scores + (size_t)bp * S_;

    for (int idx = t; idx < S_ / 4; idx += 256)
        ((float4*)ssc)[idx] = ((const float4*)srow)[idx];
    if (t == 0) cnt = 0;
    __syncthreads();

    // block max
    float m = -3.4e38f;
    for (int i = t; i < S_; i += 256) m = fmaxf(m, ssc[i]);
#pragma unroll
    for (int o = 16; o; o >>= 1) m = fmaxf(m, __shfl_xor_sync(0xffffffffu, m, o));
    if ((t & 31) == 0) red[t >> 5] = m;
    __syncthreads();
    if (t == 0) {
        float mm = red[0];
#pragma unroll
        for (int w = 1; w < 8; ++w) mm = fmaxf(mm, red[w]);
        Msh = mm;
    }
    __syncthreads();
    const float M = Msh;
    const float thr = M - 20.0f;

    // exact denominator + gather significant entries
    float ls = 0.f;
    for (int i = t; i < S_; i += 256) {
        float sc = ssc[i];
        float w = __expf(sc - M);
        ls += w;
        if (sc >= thr) {
            int k = atomicAdd(&cnt, 1);
            lst[k] = i;
            lw[k] = w;
        }
    }
#pragma unroll
    for (int o = 16; o; o >>= 1) ls += __shfl_xor_sync(0xffffffffu, ls, o);
    if ((t & 31) == 0) red[t >> 5] = ls;
    __syncthreads();
    if (t == 0) {
        float s = 0.f;
#pragma unroll
        for (int w = 0; w < 8; ++w) s += red[w];
        Lsh = s;
    }
    __syncthreads();
    const float inv = 1.0f / Lsh;
    const int n = cnt;

    // sparse context: each thread owns h = 2t, 2t+1
    const float* xb = x + (size_t)b * S_ * H_ + (t * 2);
    float a0 = 0.f, a1 = 0.f;
    for (int e = 0; e < n; ++e) {
        float2 v = *(const float2*)(xb + (size_t)lst[e] * H_);
        float w = lw[e];
        a0 += w * v.x;
        a1 += w * v.y;
    }
    const size_t o0 = (size_t)b * (P_ * H_) + (size_t)p * H_ + t * 2;
    out[o0]     = a0 * inv;
    out[o0 + 1] = a1 * inv;
}

// ---------------- launch ----------------
extern "C" void kernel_launch(void* const* d_in, const int* in_sizes, int n_in,
                              void* d_out, int out_size) {
    const float* x = (const float*)d_in[0];       // [B,S,H] f32
    const float* probes = (const float*)d_in[1];  // [P,H]  f32
    float* out = (float*)d_out;                   // [B, P*H] f32

    const int smem1 = (P_ * PSTR + 2 * TS * XSTR + P_ * SSTR) * (int)sizeof(float); // 180864
    const int smem2 = (S_ * 3) * (int)sizeof(float);                                // 98304

    cudaFuncSetAttribute(k_scores, cudaFuncAttributeMaxDynamicSharedMemorySize, smem1);
    cudaFuncSetAttribute(k_softmax_ctx, cudaFuncAttributeMaxDynamicSharedMemorySize, smem2);

    k_scores<<<B_ * NSPLIT, 256, smem1>>>(x, probes);
    k_softmax_ctx<<<B_ * P_, 256, smem2>>>(x, out);
}

// round 12
// speedup vs baseline: 1.0020x; 1.0020x over previous
#include <cuda_runtime.h>
#include <cstdint>

#define B_ 16
#define S_ 8192
#define H_ 512
#define P_ 32
#define NSPLIT 8
#define TS 512          // s-rows per tile
#define KC 8            // h per k-chunk
#define NCH (H_/KC)     // 64 chunks
#define PSTR 516        // probe smem row stride (floats) -> conflict-free
#define XSTR 12         // x-stage row stride (floats)    -> conflict-free
#define SSTR 513        // score-stage row stride

// 16 MB scratch for scores[b*P+p][s]
__device__ float g_scores[(size_t)B_ * P_ * S_];

// ---------------- helpers ----------------
__device__ __forceinline__ void ffma2(unsigned long long& d, unsigned long long a,
                                      unsigned long long b) {
    asm("fma.rn.f32x2 %0, %1, %2, %0;" : "+l"(d) : "l"(a), "l"(b));
}
__device__ __forceinline__ float2 unpk(unsigned long long v) {
    float2 r;
    asm("mov.b64 {%0,%1}, %2;" : "=f"(r.x), "=f"(r.y) : "l"(v));
    return r;
}
__device__ __forceinline__ void cp16(float* s, const float* g) {
    unsigned sa = (unsigned)__cvta_generic_to_shared(s);
    asm volatile("cp.async.cg.shared.global [%0], [%1], 16;" :: "r"(sa), "l"(g));
}
__device__ __forceinline__ void cp_commit() { asm volatile("cp.async.commit_group;"); }
template <int N>
__device__ __forceinline__ void cp_wait() { asm volatile("cp.async.wait_group %0;" :: "n"(N)); }

// ---------------- kernel 1: scores = probes @ x^T (fp32, packed f32x2) ----------------
// grid = B_*NSPLIT (=128), block = 256. Each CTA: 1024 s-rows in 2 tiles of 512.
// Thread tile 8s x 8p: s = rowt + 64*i, p = col + 4*j (col = t&3, rowt = t>>2).
__global__ void __launch_bounds__(256, 1)
k_scores(const float* __restrict__ x, const float* __restrict__ probes) {
    extern __shared__ float sm[];
    float* psm = sm;                     // P_*PSTR   = 16512 f
    float* stg = sm + P_ * PSTR;         // 2*TS*XSTR = 12288 f
    float* scs = stg + 2 * TS * XSTR;    // P_*SSTR   = 16416 f

    const int t = threadIdx.x;
    const int col = t & 3;
    const int rowt = t >> 2;
    const int b = blockIdx.x >> 3;
    const int split = blockIdx.x & 7;
    const float* xb = x + (size_t)b * S_ * H_;

    // probes -> smem (padded rows)
    for (int idx = t; idx < P_ * H_; idx += 256) {
        psm[(idx >> 9) * PSTR + (idx & 511)] = probes[idx];
    }

    for (int tile = 0; tile < 2; ++tile) {
        const int s0 = split * 1024 + tile * TS;

        unsigned long long acc[8][8];
#pragma unroll
        for (int i = 0; i < 8; ++i)
#pragma unroll
            for (int j = 0; j < 8; ++j) acc[i][j] = 0ull;

        // prologue: chunk 0 -> buf 0
        {
#pragma unroll
            for (int q = 0; q < 4; ++q) {
                int idx = t + 256 * q;
                int row = idx >> 1, seg = (idx & 1) * 4;
                cp16(stg + row * XSTR + seg, xb + (size_t)(s0 + row) * H_ + seg);
            }
            cp_commit();
        }

#pragma unroll 1
        for (int c = 0; c < NCH; ++c) {
            if (c + 1 < NCH) {
                float* dst = stg + ((c + 1) & 1) * TS * XSTR;
                const int hc1 = (c + 1) * KC;
#pragma unroll
                for (int q = 0; q < 4; ++q) {
                    int idx = t + 256 * q;
                    int row = idx >> 1, seg = (idx & 1) * 4;
                    cp16(dst + row * XSTR + seg, xb + (size_t)(s0 + row) * H_ + hc1 + seg);
                }
                cp_commit();
                cp_wait<1>();
            } else {
                cp_wait<0>();
            }
            __syncthreads();

            const float* st = stg + (c & 1) * TS * XSTR;
            const int hc = c * KC;
#pragma unroll
            for (int u = 0; u < 2; ++u) {
                ulonglong2 pvv[8];
#pragma unroll
                for (int j = 0; j < 8; ++j)
                    pvv[j] = *(const ulonglong2*)&psm[(col + 4 * j) * PSTR + hc + u * 4];
#pragma unroll
                for (int i = 0; i < 8; ++i) {
                    ulonglong2 xv = *(const ulonglong2*)&st[(rowt + 64 * i) * XSTR + u * 4];
#pragma unroll
                    for (int j = 0; j < 8; ++j) {
                        ffma2(acc[i][j], xv.x, pvv[j].x);
                        ffma2(acc[i][j], xv.y, pvv[j].y);
                    }
                }
            }
            __syncthreads();
        }

        // finalize (even+odd partials) and stage for coalesced store
#pragma unroll
        for (int j = 0; j < 8; ++j)
#pragma unroll
            for (int i = 0; i < 8; ++i) {
                float2 v = unpk(acc[i][j]);
                scs[(col + 4 * j) * SSTR + rowt + 64 * i] = v.x + v.y;
            }
        __syncthreads();

        float* grow = g_scores + (size_t)(b * P_) * S_ + s0;
        for (int idx = t; idx < P_ * TS; idx += 256) {
            int p = idx >> 9;
            int sl = idx & 511;
            grow[(size_t)p * S_ + sl] = scs[p * SSTR + sl];
        }
        __syncthreads();
    }
}

// ---------------- kernel 2: exact softmax stats + sparse context gather ----------------
// grid = B_*P_ (=512), block = 256. One CTA per (b,p).
// Exact max and exact denominator over all 8192 scores; numerator gathers only
// entries with score >= max-20 (skipped mass < 2e-5, far below 1e-3 tolerance).
__global__ void __launch_bounds__(256, 2)
k_softmax_ctx(const float* __restrict__ x, float* __restrict__ out) {
    extern __shared__ float sm2[];
    float* ssc = sm2;                    // 8192 scores
    float* lw  = sm2 + 8192;             // weights of kept entries
    int*   lst = (int*)(sm2 + 16384);    // s-indices of kept entries (cap 8192: safe)

    __shared__ float red[8];
    __shared__ float Msh, Lsh;
    __shared__ int cnt;

    const int t = threadIdx.x;
    const int bp = blockIdx.x;
    const int b = bp >> 5;
    const int p = bp & 31;
    const float* srow = g_scores + (size_t)bp * S_;

    for (int idx = t; idx < S_ / 4; idx += 256)
        ((float4*)ssc)[idx] = ((const float4*)srow)[idx];
    if (t == 0) cnt = 0;
    __syncthreads();

    // block max
    float m = -3.4e38f;
    for (int i = t; i < S_; i += 256) m = fmaxf(m, ssc[i]);
#pragma unroll
    for (int o = 16; o; o >>= 1) m = fmaxf(m, __shfl_xor_sync(0xffffffffu, m, o));
    if ((t & 31) == 0) red[t >> 5] = m;
    __syncthreads();
    if (t == 0) {
        float mm = red[0];
#pragma unroll
        for (int w = 1; w < 8; ++w) mm = fmaxf(mm, red[w]);
        Msh = mm;
    }
    __syncthreads();
    const float M = Msh;
    const float thr = M - 20.0f;

    // exact denominator + gather significant entries
    float ls = 0.f;
    for (int i = t; i < S_; i += 256) {
        float sc = ssc[i];
        float w = __expf(sc - M);
        ls += w;
        if (sc >= thr) {
            int k = atomicAdd(&cnt, 1);
            lst[k] = i;
            lw[k] = w;
        }
    }
#pragma unroll
    for (int o = 16; o; o >>= 1) ls += __shfl_xor_sync(0xffffffffu, ls, o);
    if ((t & 31) == 0) red[t >> 5] = ls;
    __syncthreads();
    if (t == 0) {
        float s = 0.f;
#pragma unroll
        for (int w = 0; w < 8; ++w) s += red[w];
        Lsh = s;
    }
    __syncthreads();
    const float inv = 1.0f / Lsh;
    const int n = cnt;

    // sparse context: each thread owns h = 2t, 2t+1
    const float* xb = x + (size_t)b * S_ * H_ + (t * 2);
    float a0 = 0.f, a1 = 0.f;
    for (int e = 0; e < n; ++e) {
        float2 v = *(const float2*)(xb + (size_t)lst[e] * H_);
        float w = lw[e];
        a0 += w * v.x;
        a1 += w * v.y;
    }
    const size_t o0 = (size_t)b * (P_ * H_) + (size_t)p * H_ + t * 2;
    out[o0]     = a0 * inv;
    out[o0 + 1] = a1 * inv;
}

// ---------------- launch ----------------
extern "C" void kernel_launch(void* const* d_in, const int* in_sizes, int n_in,
                              void* d_out, int out_size) {
    const float* x = (const float*)d_in[0];       // [B,S,H] f32
    const float* probes = (const float*)d_in[1];  // [P,H]  f32
    float* out = (float*)d_out;                   // [B, P*H] f32

    const int smem1 = (P_ * PSTR + 2 * TS * XSTR + P_ * SSTR) * (int)sizeof(float); // 180864
    const int smem2 = (S_ * 3) * (int)sizeof(float);                                // 98304

    cudaFuncSetAttribute(k_scores, cudaFuncAttributeMaxDynamicSharedMemorySize, smem1);
    cudaFuncSetAttribute(k_softmax_ctx, cudaFuncAttributeMaxDynamicSharedMemorySize, smem2);

    k_scores<<<B_ * NSPLIT, 256, smem1>>>(x, probes);
    k_softmax_ctx<<<B_ * P_, 256, smem2>>>(x, out);
}

// round 17
// speedup vs baseline: 1.8299x; 1.8263x over previous
#include <cuda_runtime.h>
#include <cuda_bf16.h>
#include <cstdint>

#define B_ 16
#define S_ 8192
#define H_ 512
#define P_ 32

// 16 MB scratch for scores[b*P+p][s]
__device__ float g_scores[(size_t)B_ * P_ * S_];

// ---------------- smem layout (bytes) ----------------
// probes [k][n] bf16, row stride 40 bf16 (80 B): 512*80 = 40960 per plane
#define PB_HI 0
#define PB_LO 40960
// x tile [s=128][k=64] bf16, row stride 72 bf16 (144 B): 128*144 = 18432 per plane
#define XBUF 81920
#define XPLANE 18432
#define XBUFSZ (2 * XPLANE)      // hi + lo = 36864 per buffer
#define SM_TOTAL (XBUF + 2 * XBUFSZ)  // 155648

// ---------------- helpers ----------------
__device__ __forceinline__ uint32_t smem_u32(const void* p) {
    uint32_t a;
    asm("{ .reg .u64 t; cvta.to.shared.u64 t, %1; cvt.u32.u64 %0, t; }" : "=r"(a) : "l"(p));
    return a;
}
__device__ __forceinline__ void ldsm4(uint32_t* r, uint32_t addr) {
    asm volatile("ldmatrix.sync.aligned.m8n8.x4.shared.b16 {%0,%1,%2,%3}, [%4];"
                 : "=r"(r[0]), "=r"(r[1]), "=r"(r[2]), "=r"(r[3]) : "r"(addr));
}
__device__ __forceinline__ void ldsm4t(uint32_t* r, uint32_t addr) {
    asm volatile("ldmatrix.sync.aligned.m8n8.x4.trans.shared.b16 {%0,%1,%2,%3}, [%4];"
                 : "=r"(r[0]), "=r"(r[1]), "=r"(r[2]), "=r"(r[3]) : "r"(addr));
}
__device__ __forceinline__ void mma16816(float* c, const uint32_t* a, const uint32_t* b) {
    asm volatile(
        "mma.sync.aligned.m16n8k16.row.col.f32.bf16.bf16.f32 "
        "{%0,%1,%2,%3}, {%4,%5,%6,%7}, {%8,%9}, {%0,%1,%2,%3};"
        : "+f"(c[0]), "+f"(c[1]), "+f"(c[2]), "+f"(c[3])
        : "r"(a[0]), "r"(a[1]), "r"(a[2]), "r"(a[3]), "r"(b[0]), "r"(b[1]));
}
__device__ __forceinline__ uint32_t bf2bits(__nv_bfloat162 v) {
    return *reinterpret_cast<uint32_t*>(&v);
}
__device__ __forceinline__ void split4(float4 v, uint2& hi, uint2& lo) {
    __nv_bfloat162 h01 = __floats2bfloat162_rn(v.x, v.y);
    __nv_bfloat162 h23 = __floats2bfloat162_rn(v.z, v.w);
    float2 f01 = __bfloat1622float2(h01);
    float2 f23 = __bfloat1622float2(h23);
    __nv_bfloat162 l01 = __floats2bfloat162_rn(v.x - f01.x, v.y - f01.y);
    __nv_bfloat162 l23 = __floats2bfloat162_rn(v.z - f23.x, v.w - f23.y);
    hi = make_uint2(bf2bits(h01), bf2bits(h23));
    lo = make_uint2(bf2bits(l01), bf2bits(l23));
}

// ---------------- kernel 1: scores = x @ probes^T via HMMA bf16x3 ----------------
// grid = B*64 (one CTA per 128-row s-tile), block = 256 (8 warps x m16, full N=32)
__global__ void __launch_bounds__(256, 1)
k_scores(const float* __restrict__ x, const float* __restrict__ probes) {
    extern __shared__ char smem[];
    const uint32_t sb = smem_u32(smem);
    const int t = threadIdx.x, w = t >> 5, lane = t & 31;
    const int b = blockIdx.x >> 6;
    const int s0 = (blockIdx.x & 63) << 7;
    const float* xb = x + (size_t)b * S_ * H_;

    // ---- prefetch x chunk 0 (hide latency behind probe conversion) ----
    float4 vv[8];
#pragma unroll
    for (int i = 0; i < 8; ++i) {
        int idx = t + 256 * i;
        int row = idx >> 4, c4 = idx & 15;
        vv[i] = *(const float4*)(xb + (size_t)(s0 + row) * H_ + c4 * 4);
    }

    // ---- probes fp32 [p][h] -> smem bf16 hi/lo in [k][n] layout (stride 40 bf16) ----
    {
        const int p = t & 31;
        const int hb = (t >> 5) << 2;  // 0,4,...,28
#pragma unroll
        for (int i = 0; i < 16; ++i) {
            int h0 = hb + i * 32;
            float4 v = *(const float4*)(probes + p * H_ + h0);
            float hv[4] = {v.x, v.y, v.z, v.w};
#pragma unroll
            for (int e = 0; e < 4; ++e) {
                __nv_bfloat16 hi = __float2bfloat16_rn(hv[e]);
                __nv_bfloat16 lo = __float2bfloat16_rn(hv[e] - __bfloat162float(hi));
                *(__nv_bfloat16*)(smem + PB_HI + (size_t)(h0 + e) * 80 + p * 2) = hi;
                *(__nv_bfloat16*)(smem + PB_LO + (size_t)(h0 + e) * 80 + p * 2) = lo;
            }
        }
    }
    __syncthreads();

    // ---- mma mainloop over 8 k-chunks of 64 ----
    float acc[4][4];
#pragma unroll
    for (int j = 0; j < 4; ++j)
#pragma unroll
        for (int e = 0; e < 4; ++e) acc[j][e] = 0.f;

    // ldmatrix lane address components
    const int a_row = (lane & 7) + ((lane >> 3) & 1) * 8;   // A: s-row within tile
    const int a_kc = ((lane >> 4) & 1) * 8;                 // A: k col offset
    const int b_kr = (lane & 7) + ((lane >> 3) & 1) * 8;    // B: k row offset
    const int b_nc = ((lane >> 4) & 1) * 8;                 // B: n col offset

#pragma unroll 1
    for (int c = 0; c < 8; ++c) {
        const int buf = c & 1;
        const uint32_t xbase = sb + XBUF + buf * XBUFSZ;

        // convert + store current chunk
#pragma unroll
        for (int i = 0; i < 8; ++i) {
            int idx = t + 256 * i;
            int row = idx >> 4, c4 = idx & 15;
            uint2 hi, lo;
            split4(vv[i], hi, lo);
            *(uint2*)(smem + XBUF + buf * XBUFSZ + row * 144 + c4 * 8) = hi;
            *(uint2*)(smem + XBUF + buf * XBUFSZ + XPLANE + row * 144 + c4 * 8) = lo;
        }
        // prefetch next chunk
        if (c < 7) {
            const int hb = (c + 1) * 64;
#pragma unroll
            for (int i = 0; i < 8; ++i) {
                int idx = t + 256 * i;
                int row = idx >> 4, c4 = idx & 15;
                vv[i] = *(const float4*)(xb + (size_t)(s0 + row) * H_ + hb + c4 * 4);
            }
        }
        __syncthreads();

#pragma unroll
        for (int kk = 0; kk < 4; ++kk) {
            uint32_t aoff = (uint32_t)((16 * w + a_row) * 144 + (kk * 16 + a_kc) * 2);
            uint32_t ah[4], al[4];
            ldsm4(ah, xbase + aoff);
            ldsm4(al, xbase + XPLANE + aoff);

            const int kb = c * 64 + kk * 16 + b_kr;
            uint32_t bh[8], bl[8];
            {
                uint32_t bo0 = (uint32_t)(kb * 80 + b_nc * 2);        // q=0: n 0..15
                uint32_t bo1 = (uint32_t)(kb * 80 + (16 + b_nc) * 2); // q=1: n 16..31
                ldsm4t(bh + 0, sb + PB_HI + bo0);
                ldsm4t(bh + 4, sb + PB_HI + bo1);
                ldsm4t(bl + 0, sb + PB_LO + bo0);
                ldsm4t(bl + 4, sb + PB_LO + bo1);
            }
            // hi*hi
            mma16816(acc[0], ah, bh + 0);
            mma16816(acc[1], ah, bh + 2);
            mma16816(acc[2], ah, bh + 4);
            mma16816(acc[3], ah, bh + 6);
            // hi*lo
            mma16816(acc[0], ah, bl + 0);
            mma16816(acc[1], ah, bl + 2);
            mma16816(acc[2], ah, bl + 4);
            mma16816(acc[3], ah, bl + 6);
            // lo*hi
            mma16816(acc[0], al, bh + 0);
            mma16816(acc[1], al, bh + 2);
            mma16816(acc[2], al, bh + 4);
            mma16816(acc[3], al, bh + 6);
        }
    }
    __syncthreads();

    // ---- epilogue: acc -> smem transpose -> coalesced p-major STG ----
    float* scs = (float*)(smem + XBUF);  // [32][132]
    {
        const int r = 16 * w + (lane >> 2);
#pragma unroll
        for (int j = 0; j < 4; ++j) {
            int p = 8 * j + 2 * (lane & 3);
            scs[p * 132 + r] = acc[j][0];
            scs[(p + 1) * 132 + r] = acc[j][1];
            scs[p * 132 + r + 8] = acc[j][2];
            scs[(p + 1) * 132 + r + 8] = acc[j][3];
        }
    }
    __syncthreads();
#pragma unroll
    for (int i = 0; i < 16; ++i) {
        int idx = t + 256 * i;
        int p = idx >> 7, sc = idx & 127;
        g_scores[(size_t)(b * P_ + p) * S_ + s0 + sc] = scs[p * 132 + sc];
    }
}

// ---------------- kernel 2: exact softmax stats + sparse context gather ----------------
// grid = B*P (=512), block = 256. One CTA per (b,p). Scores read straight from
// gmem (2nd pass L2-hit); only smem is the kept-entry list (32 KB -> high occ).
#define CAP 4096
__global__ void __launch_bounds__(256)
k_softmax_ctx(const float* __restrict__ x, float* __restrict__ out) {
    extern __shared__ float sm2[];
    float* lw = sm2;            // CAP floats
    int* lst = (int*)(sm2 + CAP);

    __shared__ float red[8];
    __shared__ float Msh, Lsh;
    __shared__ int cnt;

    const int t = threadIdx.x;
    const int bp = blockIdx.x;
    const int b = bp >> 5;
    const int p = bp & 31;
    const float* srow = g_scores + (size_t)bp * S_;

    if (t == 0) cnt = 0;
    __syncthreads();

    // pass 1: exact max
    float m = -3.4e38f;
    for (int i4 = t; i4 < S_ / 4; i4 += 256) {
        float4 v = ((const float4*)srow)[i4];
        m = fmaxf(m, fmaxf(fmaxf(v.x, v.y), fmaxf(v.z, v.w)));
    }
#pragma unroll
    for (int o = 16; o; o >>= 1) m = fmaxf(m, __shfl_xor_sync(0xffffffffu, m, o));
    if ((t & 31) == 0) red[t >> 5] = m;
    __syncthreads();
    if (t == 0) {
        float mm = red[0];
#pragma unroll
        for (int q = 1; q < 8; ++q) mm = fmaxf(mm, red[q]);
        Msh = mm;
    }
    __syncthreads();
    const float M = Msh;
    const float thr = M - 20.0f;

    // pass 2: exact denominator + gather significant entries
    float ls = 0.f;
    for (int i = t; i < S_; i += 256) {
        float sc = srow[i];
        float wgt = __expf(sc - M);
        ls += wgt;
        if (sc >= thr) {
            int k = atomicAdd(&cnt, 1);
            if (k < CAP) {
                lst[k] = i;
                lw[k] = wgt;
            }
        }
    }
#pragma unroll
    for (int o = 16; o; o >>= 1) ls += __shfl_xor_sync(0xffffffffu, ls, o);
    if ((t & 31) == 0) red[t >> 5] = ls;
    __syncthreads();
    if (t == 0) {
        float s = 0.f;
#pragma unroll
        for (int q = 0; q < 8; ++q) s += red[q];
        Lsh = s;
    }
    __syncthreads();
    const float inv = 1.0f / Lsh;
    const int n = min(cnt, CAP);

    // sparse context: each thread owns h = 2t, 2t+1
    const float* xb = x + (size_t)b * S_ * H_ + (t * 2);
    float a0 = 0.f, a1 = 0.f;
    for (int e = 0; e < n; ++e) {
        float2 v = *(const float2*)(xb + (size_t)lst[e] * H_);
        float wgt = lw[e];
        a0 += wgt * v.x;
        a1 += wgt * v.y;
    }
    const size_t o0 = (size_t)b * (P_ * H_) + (size_t)p * H_ + t * 2;
    out[o0] = a0 * inv;
    out[o0 + 1] = a1 * inv;
}

// ---------------- launch ----------------
extern "C" void kernel_launch(void* const* d_in, const int* in_sizes, int n_in,
                              void* d_out, int out_size) {
    const float* x = (const float*)d_in[0];       // [B,S,H] f32
    const float* probes = (const float*)d_in[1];  // [P,H]  f32
    float* out = (float*)d_out;                   // [B, P*H] f32

    const int smem1 = SM_TOTAL;              // 155648
    const int smem2 = CAP * 2 * (int)sizeof(float);  // 32768

    cudaFuncSetAttribute(k_scores, cudaFuncAttributeMaxDynamicSharedMemorySize, smem1);
    cudaFuncSetAttribute(k_softmax_ctx, cudaFuncAttributeMaxDynamicSharedMemorySize, smem2);

    k_scores<<<B_ * 64, 256, smem1>>>(x, probes);
    k_softmax_ctx<<<B_ * P_, 256, smem2>>>(x, out);
}